// round 10
// baseline (speedup 1.0000x reference)
#include <cuda_runtime.h>

// ============================================================================
// ObjectDetector post-processing on GB300 — v5.
//   score_kernel   : stream cls (4x-batched float4 loads), per-block 256-bin
//                    LOGIT histogram partials; LAST block per segment (ticket)
//                    reduces partials -> threshold bin -> g_tbin
//   compact_kernel : re-stream cls (L2-hot, 4x-batched); exact
//                    sigmoid+decode+validity mask above g_tbin; append keys
//   nms_kernel     : register bitonic sort (1024 thr, shfl for j<=16),
//                    decode top-300, ON-DEMAND per-kept-row IoU via ballot,
//                    greedy walk (early exit at 10), write output
// ============================================================================

#define BATCH 16
#define KPRE  300
#define KOUT  10
#define CAP   1024
#define NBIN  256
#define NSAFE 700
#define XB    8       // blocks per (b,level) segment (2^32 % XB == 0)
#define UN    4       // float4 loads batched per thread per iteration

__device__ unsigned int       g_ph[64 * XB * NBIN];   // partial histograms
__device__ unsigned int       g_tick[64];             // monotonic arrival tickets
__device__ int                g_tbin[64];
__device__ int                g_cnt[64 * 32];         // padded counters
__device__ unsigned long long g_keys[64 * CAP];

// level constants: Nl = 9*HW2
__constant__ int c_Nl[4]  = {147456, 36864, 9216, 2304};
__constant__ int c_sh2[4] = {14, 12, 10, 8};          // log2(HW2)

// ---------------------------------------------------------------------------
// Exact replication of reference decode (no FMA contraction; libdevice expf)
// ---------------------------------------------------------------------------
__device__ __forceinline__ void decode_box(const float4 A,
                                           float d0, float d1, float d2, float d3,
                                           float& x1, float& y1, float& x2, float& y2,
                                           bool& valid)
{
    float w  = __fsub_rn(A.z, A.x);
    float h  = __fsub_rn(A.w, A.y);
    float cx = __fadd_rn(A.x, __fmul_rn(0.5f, w));
    float cy = __fadd_rn(A.y, __fmul_rn(0.5f, h));
    d0 = fminf(fmaxf(d0, -2.0f), 2.0f);
    d1 = fminf(fmaxf(d1, -2.0f), 2.0f);
    d2 = fminf(fmaxf(d2, -2.0f), 2.0f);
    d3 = fminf(fmaxf(d3, -2.0f), 2.0f);
    float px = __fadd_rn(cx, __fmul_rn(d0, w));
    float py = __fadd_rn(cy, __fmul_rn(d1, h));
    float pw = __fmul_rn(w, expf(d2));
    float ph = __fmul_rn(h, expf(d3));
    float hpw = __fmul_rn(0.5f, pw);
    float hph = __fmul_rn(0.5f, ph);
    x1 = fminf(fmaxf(__fsub_rn(px, hpw), 0.0f), 1024.0f);
    y1 = fminf(fmaxf(__fsub_rn(py, hph), 0.0f), 1024.0f);
    x2 = fminf(fmaxf(__fadd_rn(px, hpw), 0.0f), 1024.0f);
    y2 = fminf(fmaxf(__fadd_rn(py, hph), 0.0f), 1024.0f);
    float bw = __fsub_rn(x2, x1);
    float bh = __fsub_rn(y2, y1);
    valid = (bw > 1.0f) && (bh > 1.0f) && (bw < 2000.0f) && (bh < 2000.0f);
}

// bit-identical bin computation used by BOTH score and compact passes
__device__ __forceinline__ int logit_bin(float lgt)
{
    return min(NBIN - 1, (int)(lgt * 42.0f));
}

// ---------------------------------------------------------------------------
// Pass 1: logit histogram + last-block threshold. grid (XB, 64), block 256.
// ---------------------------------------------------------------------------
__global__ __launch_bounds__(256) void score_kernel(
    const float* __restrict__ c0, const float* __restrict__ c1,
    const float* __restrict__ c2, const float* __restrict__ c3)
{
    __shared__ unsigned int sh[NBIN];
    __shared__ int s_last;
    const int y = blockIdx.y;
    const int b = y >> 2, l = y & 3;
    const int tid = threadIdx.x;
    sh[tid] = 0u;
    if (blockIdx.x == 0 && tid == 0) g_cnt[y * 32] = 0;
    __syncthreads();

    const float* cls = (l == 0) ? c0 : (l == 1) ? c1 : (l == 2) ? c2 : c3;
    const int Nl = c_Nl[l];
    const float* seg = cls + (size_t)b * Nl;
    const int quads = Nl >> 2;

    // 4 independent float4 loads in flight per iteration
    for (int base = blockIdx.x * (256 * UN); base < quads; base += XB * 256 * UN) {
        float4 v[UN];
        bool ok[UN];
        #pragma unroll
        for (int k = 0; k < UN; k++) {
            int q = base + k * 256 + tid;
            ok[k] = (q < quads);
            if (ok[k]) v[k] = *(const float4*)(seg + ((size_t)q << 2));
        }
        #pragma unroll
        for (int k = 0; k < UN; k++) {
            if (ok[k]) {
                if (v[k].x > 0.0f) atomicAdd(&sh[logit_bin(v[k].x)], 1u);
                if (v[k].y > 0.0f) atomicAdd(&sh[logit_bin(v[k].y)], 1u);
                if (v[k].z > 0.0f) atomicAdd(&sh[logit_bin(v[k].z)], 1u);
                if (v[k].w > 0.0f) atomicAdd(&sh[logit_bin(v[k].w)], 1u);
            }
        }
    }
    __syncthreads();
    g_ph[(size_t)(y * XB + blockIdx.x) * NBIN + tid] = sh[tid];
    __syncthreads();

    // ticket: last-arriving block of this segment computes the threshold
    if (tid == 0) {
        __threadfence();
        unsigned int pos = atomicAdd(&g_tick[y], 1u);
        s_last = ((pos % XB) == XB - 1);
    }
    __syncthreads();
    if (s_last) {
        __threadfence();
        unsigned int s = 0;
        #pragma unroll
        for (int x = 0; x < XB; x++)
            s += g_ph[(size_t)(y * XB + x) * NBIN + tid];
        sh[tid] = s;
        __syncthreads();
        if (tid == 0) {
            unsigned int cum = 0;
            int t = 0;
            for (int i = NBIN - 1; i >= 0; --i) {
                cum += sh[i];
                if (cum >= NSAFE) { t = i; break; }
            }
            g_tbin[y] = t;
        }
    }
}

// ---------------------------------------------------------------------------
// Pass 2: compact keys with the exact mask. grid (XB, 64), block 256.
// ---------------------------------------------------------------------------
__global__ __launch_bounds__(256) void compact_kernel(
    const float* __restrict__ c0, const float* __restrict__ c1,
    const float* __restrict__ c2, const float* __restrict__ c3,
    const float* __restrict__ bx0, const float* __restrict__ bx1,
    const float* __restrict__ bx2, const float* __restrict__ bx3,
    const float* __restrict__ an0, const float* __restrict__ an1,
    const float* __restrict__ an2, const float* __restrict__ an3)
{
    const int y = blockIdx.y;
    const int b = y >> 2, l = y & 3;
    const int tid = threadIdx.x;
    const int t = g_tbin[y];

    const float* cls = (l == 0) ? c0 : (l == 1) ? c1 : (l == 2) ? c2 : c3;
    const float* box = (l == 0) ? bx0 : (l == 1) ? bx1 : (l == 2) ? bx2 : bx3;
    const float* anc = (l == 0) ? an0 : (l == 1) ? an1 : (l == 2) ? an2 : an3;
    const int Nl  = c_Nl[l];
    const int sh2 = c_sh2[l];
    const int HW2 = 1 << sh2;

    const float* seg  = cls + (size_t)b * Nl;
    const float* boxb = box + ((size_t)b * 36 << sh2);
    const int quads = Nl >> 2;

    for (int base = blockIdx.x * (256 * UN); base < quads; base += XB * 256 * UN) {
        float4 v[UN];
        bool ok[UN];
        #pragma unroll
        for (int k = 0; k < UN; k++) {
            int q = base + k * 256 + tid;
            ok[k] = (q < quads);
            if (ok[k]) v[k] = *(const float4*)(seg + ((size_t)q << 2));
        }
        #pragma unroll
        for (int k = 0; k < UN; k++) {
            if (!ok[k]) continue;
            const int q = base + k * 256 + tid;
            const float* pv = (const float*)&v[k];
            #pragma unroll
            for (int i = 0; i < 4; i++) {
                float lgt = pv[i];
                if (lgt > 0.0f && logit_bin(lgt) >= t) {
                    // exact reference mask
                    float sc = __fdiv_rn(1.0f, __fadd_rn(1.0f, expf(-lgt)));
                    int n   = (q << 2) + i;
                    int a   = n >> sh2;
                    int pix = n & (HW2 - 1);
                    const float* bp = boxb + (((size_t)a * 4) << sh2) + pix;
                    float d0 = __ldg(bp);
                    float d1 = __ldg(bp + HW2);
                    float d2 = __ldg(bp + 2 * HW2);
                    float d3 = __ldg(bp + 3 * HW2);
                    float4 A = *(const float4*)(anc + ((size_t)n << 2));
                    float x1, y1c, x2, y2; bool valid;
                    decode_box(A, d0, d1, d2, d3, x1, y1c, x2, y2, valid);
                    if (valid && sc > 0.5f) {
                        int pos = atomicAdd(&g_cnt[y * 32], 1);
                        if (pos < CAP) {
                            g_keys[(size_t)y * CAP + pos] =
                                ((unsigned long long)__float_as_uint(sc) << 32) |
                                (unsigned long long)(~(unsigned int)n);
                        }
                    }
                }
            }
        }
    }
}

// ---------------------------------------------------------------------------
// Pass 3: register bitonic sort + decode + on-demand-row greedy NMS.
// One block (1024 threads) per (b,level).
// ---------------------------------------------------------------------------
__global__ __launch_bounds__(1024) void nms_kernel(
    const float* __restrict__ bx0, const float* __restrict__ bx1,
    const float* __restrict__ bx2, const float* __restrict__ bx3,
    const float* __restrict__ an0, const float* __restrict__ an1,
    const float* __restrict__ an2, const float* __restrict__ an3,
    float* __restrict__ out, int out_size)
{
    __shared__ unsigned long long sbuf[CAP];
    __shared__ float sx1[KPRE], sy1[KPRE], sx2[KPRE], sy2[KPRE], ssc[KPRE], sar[KPRE];
    __shared__ unsigned long long rm[5];       // running suppression mask
    __shared__ int keptIdx[KOUT];
    __shared__ int s_next, s_kc;

    const int bl  = blockIdx.x;
    const int b   = bl >> 2;
    const int lvl = bl & 3;
    const int tid = threadIdx.x;

    const int M = min(g_cnt[bl * 32], CAP);
    unsigned long long v = (tid < M) ? g_keys[(size_t)bl * CAP + tid] : 0ULL;

    // ---- bitonic sort, descending; key[tid] lives in register v ----
    #pragma unroll
    for (int k = 2; k <= CAP; k <<= 1) {
        // shared-exchange stages (cross-warp)
        for (int j = k >> 1; j >= 32; j >>= 1) {
            sbuf[tid] = v;
            __syncthreads();
            unsigned long long u = sbuf[tid ^ j];
            bool lower   = (tid & j) == 0;
            bool blockUp = (tid & k) == 0;
            bool wantMax = (lower == blockUp);
            v = ((v > u) == wantMax) ? v : u;
            __syncthreads();
        }
        // intra-warp stages via shfl
        int jmax = (k >> 1) < 16 ? (k >> 1) : 16;
        for (int j = jmax; j >= 1; j >>= 1) {
            unsigned long long u = __shfl_xor_sync(0xFFFFFFFFu, v, j);
            bool lower   = (tid & j) == 0;
            bool blockUp = (tid & k) == 0;
            bool wantMax = (lower == blockUp);
            v = ((v > u) == wantMax) ? v : u;
        }
    }

    const int K = min(M, KPRE);
    const float* BX = (lvl == 0) ? bx0 : (lvl == 1) ? bx1 : (lvl == 2) ? bx2 : bx3;
    const float* AN = (lvl == 0) ? an0 : (lvl == 1) ? an1 : (lvl == 2) ? an2 : an3;
    const int sh2   = c_sh2[lvl];
    const int HW2   = 1 << sh2;

    // ---- decode top-K: thread tid owns sorted element tid ----
    if (tid < K) {
        unsigned int n = ~((unsigned int)v);
        float sc = __uint_as_float((unsigned int)(v >> 32));
        int a   = (int)(n >> sh2);
        int pix = (int)(n & (HW2 - 1));
        const float* bp = BX + (((size_t)b * 36 + (size_t)a * 4) << sh2) + pix;
        float d0 = __ldg(bp);
        float d1 = __ldg(bp + HW2);
        float d2 = __ldg(bp + 2 * HW2);
        float d3 = __ldg(bp + 3 * HW2);
        float4 A = *(const float4*)(AN + ((size_t)n << 2));
        float x1, y1, x2, y2; bool valid;
        decode_box(A, d0, d1, d2, d3, x1, y1, x2, y2, valid);
        sx1[tid] = x1; sy1[tid] = y1; sx2[tid] = x2; sy2[tid] = y2; ssc[tid] = sc;
        sar[tid] = __fmul_rn(__fsub_rn(x2, x1), __fsub_rn(y2, y1));
    }
    if (tid < 5) rm[tid] = 0ULL;
    if (tid == 0) { s_next = 0; s_kc = 0; }

    // ---- greedy walk with on-demand suppression rows ----
    for (;;) {
        __syncthreads();
        const int i  = s_next;
        const int kc = s_kc;
        if (i >= K || kc >= KOUT) break;

        // all threads: one IoU of row i vs column tid
        bool supb = false;
        if (tid > i && tid < K) {
            float xx1 = fmaxf(sx1[i], sx1[tid]);
            float yy1 = fmaxf(sy1[i], sy1[tid]);
            float xx2 = fminf(sx2[i], sx2[tid]);
            float yy2 = fminf(sy2[i], sy2[tid]);
            float iw = fmaxf(__fsub_rn(xx2, xx1), 0.0f);
            float ih = fmaxf(__fsub_rn(yy2, yy1), 0.0f);
            float inter = __fmul_rn(iw, ih);
            float den = __fadd_rn(__fsub_rn(__fadd_rn(sar[i], sar[tid]), inter), 1e-9f);
            supb = (__fdiv_rn(inter, den) > 0.3f);
        }
        unsigned int bal = __ballot_sync(0xFFFFFFFFu, supb);
        if ((tid & 31) == 0 && bal) {
            unsigned long long w64 = (unsigned long long)bal << (tid & 32);
            atomicOr(&rm[tid >> 6], w64);
        }
        if (tid == 0) keptIdx[kc] = i;
        __syncthreads();
        if (tid == 0) {
            s_kc = kc + 1;
            int j = i + 1;
            while (j < K && ((rm[j >> 6] >> (j & 63)) & 1ULL)) j++;
            s_next = j;
        }
    }
    const int keptCnt = s_kc;   // uniform: read after the breaking barrier

    if (tid < KOUT) {
        float o0 = 0.f, o1 = 0.f, o2 = 0.f, o3 = 0.f, o4 = 0.f, vv = 0.f;
        if (tid < keptCnt) {
            int i = keptIdx[tid];
            o0 = sx1[i]; o1 = sy1[i]; o2 = sx2[i]; o3 = sy2[i]; o4 = ssc[i];
            vv = 1.0f;
        }
        size_t row = (size_t)b * 40 + lvl * 10 + tid;
        out[row * 5 + 0] = o0;
        out[row * 5 + 1] = o1;
        out[row * 5 + 2] = o2;
        out[row * 5 + 3] = o3;
        out[row * 5 + 4] = o4;
        if (out_size >= BATCH * 40 * 5 + BATCH * 40)
            out[(size_t)BATCH * 40 * 5 + row] = vv;   // valid mask as float
    }
}

// ---------------------------------------------------------------------------
extern "C" void kernel_launch(void* const* d_in, const int* in_sizes, int n_in,
                              void* d_out, int out_size)
{
    const float *cls[4], *box[4], *anc[4];
    bool interleaved = (n_in >= 2) && (in_sizes[1] == 4 * in_sizes[0]);
    for (int l = 0; l < 4; l++) {
        if (interleaved) {
            cls[l] = (const float*)d_in[3 * l + 0];
            box[l] = (const float*)d_in[3 * l + 1];
            anc[l] = (const float*)d_in[3 * l + 2];
        } else {
            cls[l] = (const float*)d_in[l];
            box[l] = (const float*)d_in[4 + l];
            anc[l] = (const float*)d_in[8 + l];
        }
    }

    dim3 gseg(XB, 64);
    score_kernel<<<gseg, 256>>>(cls[0], cls[1], cls[2], cls[3]);
    compact_kernel<<<gseg, 256>>>(cls[0], cls[1], cls[2], cls[3],
                                  box[0], box[1], box[2], box[3],
                                  anc[0], anc[1], anc[2], anc[3]);
    nms_kernel<<<64, 1024>>>(box[0], box[1], box[2], box[3],
                             anc[0], anc[1], anc[2], anc[3],
                             (float*)d_out, out_size);
}

// round 11
// speedup vs baseline: 1.2068x; 1.2068x over previous
#include <cuda_runtime.h>

// ============================================================================
// ObjectDetector post-processing on GB300 — v6.
// Flat proportional grid: one block = 1024 quads (256 thr x 4 float4 loads,
// all independent). Blocks per (b,level): {36,9,3,1} -> 49 per batch, 784 total.
//   score_kernel   : logit histogram partials; last-arriving block per segment
//                    (ticket) reduces -> threshold bin -> g_tbin
//   compact_kernel : same decomposition; exact sigmoid+decode+validity mask
//                    above g_tbin; append (score,~idx) keys
//   nms_kernel     : register bitonic sort + on-demand-row greedy NMS
// ============================================================================

#define BATCH 16
#define KPRE  300
#define KOUT  10
#define CAP   1024
#define NBIN  256
#define NSAFE 700
#define QPB   1024    // quads per block
#define XBMAX 36
#define BPB   49      // blocks per batch image
#define NBLK  (BPB * BATCH)

__device__ unsigned int       g_ph[64 * XBMAX * NBIN]; // partial histograms
__device__ unsigned int       g_tick[64];              // arrival tickets
__device__ int                g_tbin[64];
__device__ int                g_cnt[64 * 32];          // padded counters
__device__ unsigned long long g_keys[64 * CAP];

// level constants: Nl = 9*HW2, quads = Nl/4
__constant__ int c_quads[4] = {36864, 9216, 2304, 576};
__constant__ int c_sh2[4]   = {14, 12, 10, 8};         // log2(HW2)
__constant__ int c_xbl[4]   = {36, 9, 3, 1};           // blocks per segment

// ---------------------------------------------------------------------------
__device__ __forceinline__ void decode_box(const float4 A,
                                           float d0, float d1, float d2, float d3,
                                           float& x1, float& y1, float& x2, float& y2,
                                           bool& valid)
{
    float w  = __fsub_rn(A.z, A.x);
    float h  = __fsub_rn(A.w, A.y);
    float cx = __fadd_rn(A.x, __fmul_rn(0.5f, w));
    float cy = __fadd_rn(A.y, __fmul_rn(0.5f, h));
    d0 = fminf(fmaxf(d0, -2.0f), 2.0f);
    d1 = fminf(fmaxf(d1, -2.0f), 2.0f);
    d2 = fminf(fmaxf(d2, -2.0f), 2.0f);
    d3 = fminf(fmaxf(d3, -2.0f), 2.0f);
    float px = __fadd_rn(cx, __fmul_rn(d0, w));
    float py = __fadd_rn(cy, __fmul_rn(d1, h));
    float pw = __fmul_rn(w, expf(d2));
    float ph = __fmul_rn(h, expf(d3));
    float hpw = __fmul_rn(0.5f, pw);
    float hph = __fmul_rn(0.5f, ph);
    x1 = fminf(fmaxf(__fsub_rn(px, hpw), 0.0f), 1024.0f);
    y1 = fminf(fmaxf(__fsub_rn(py, hph), 0.0f), 1024.0f);
    x2 = fminf(fmaxf(__fadd_rn(px, hpw), 0.0f), 1024.0f);
    y2 = fminf(fmaxf(__fadd_rn(py, hph), 0.0f), 1024.0f);
    float bw = __fsub_rn(x2, x1);
    float bh = __fsub_rn(y2, y1);
    valid = (bw > 1.0f) && (bh > 1.0f) && (bw < 2000.0f) && (bh < 2000.0f);
}

__device__ __forceinline__ int logit_bin(float lgt)
{
    return min(NBIN - 1, (int)(lgt * 42.0f));
}

// flat block id -> (b, l, xb)
__device__ __forceinline__ void map_block(int bk, int& b, int& l, int& xb)
{
    b = bk / BPB;
    int r = bk - b * BPB;
    if      (r < 36) { l = 0; xb = r; }
    else if (r < 45) { l = 1; xb = r - 36; }
    else if (r < 48) { l = 2; xb = r - 45; }
    else             { l = 3; xb = 0; }
}

// ---------------------------------------------------------------------------
// Pass 1: logit histogram + last-block threshold. grid NBLK, block 256.
// ---------------------------------------------------------------------------
__global__ __launch_bounds__(256) void score_kernel(
    const float* __restrict__ c0, const float* __restrict__ c1,
    const float* __restrict__ c2, const float* __restrict__ c3)
{
    __shared__ unsigned int sh[NBIN];
    __shared__ int s_last;
    int b, l, xb;
    map_block(blockIdx.x, b, l, xb);
    const int y   = b * 4 + l;
    const int tid = threadIdx.x;
    sh[tid] = 0u;
    if (xb == 0 && tid == 0) g_cnt[y * 32] = 0;
    __syncthreads();

    const float* cls = (l == 0) ? c0 : (l == 1) ? c1 : (l == 2) ? c2 : c3;
    const int quads = c_quads[l];
    const float* seg = cls + (((size_t)b * 9 * quads) << 2) / 4 * 4; // b*Nl
    // Nl = quads*4
    seg = cls + (size_t)b * ((size_t)quads << 2);

    const int base = xb * QPB;
    float4 v[4];
    bool ok[4];
    #pragma unroll
    for (int k = 0; k < 4; k++) {
        int q = base + k * 256 + tid;
        ok[k] = (q < quads);
        if (ok[k]) v[k] = *(const float4*)(seg + ((size_t)q << 2));
    }
    #pragma unroll
    for (int k = 0; k < 4; k++) {
        if (ok[k]) {
            if (v[k].x > 0.0f) atomicAdd(&sh[logit_bin(v[k].x)], 1u);
            if (v[k].y > 0.0f) atomicAdd(&sh[logit_bin(v[k].y)], 1u);
            if (v[k].z > 0.0f) atomicAdd(&sh[logit_bin(v[k].z)], 1u);
            if (v[k].w > 0.0f) atomicAdd(&sh[logit_bin(v[k].w)], 1u);
        }
    }
    __syncthreads();
    g_ph[(size_t)(y * XBMAX + xb) * NBIN + tid] = sh[tid];
    __syncthreads();

    // ticket: last-arriving block of this segment computes the threshold
    const int xbl = c_xbl[l];
    if (tid == 0) {
        __threadfence();
        unsigned int pos = atomicAdd(&g_tick[y], 1u);
        s_last = (pos == (unsigned int)(xbl - 1));
    }
    __syncthreads();
    if (s_last) {
        __threadfence();
        unsigned int s = 0;
        for (int x = 0; x < xbl; x++)
            s += g_ph[(size_t)(y * XBMAX + x) * NBIN + tid];
        sh[tid] = s;
        __syncthreads();
        if (tid == 0) {
            unsigned int cum = 0;
            int t = 0;
            for (int i = NBIN - 1; i >= 0; --i) {
                cum += sh[i];
                if (cum >= NSAFE) { t = i; break; }
            }
            g_tbin[y] = t;
            g_tick[y] = 0u;   // reset for next launch/replay
        }
    }
}

// ---------------------------------------------------------------------------
// Pass 2: compact keys with the exact mask. grid NBLK, block 256.
// ---------------------------------------------------------------------------
__global__ __launch_bounds__(256) void compact_kernel(
    const float* __restrict__ c0, const float* __restrict__ c1,
    const float* __restrict__ c2, const float* __restrict__ c3,
    const float* __restrict__ bx0, const float* __restrict__ bx1,
    const float* __restrict__ bx2, const float* __restrict__ bx3,
    const float* __restrict__ an0, const float* __restrict__ an1,
    const float* __restrict__ an2, const float* __restrict__ an3)
{
    int b, l, xb;
    map_block(blockIdx.x, b, l, xb);
    const int y   = b * 4 + l;
    const int tid = threadIdx.x;
    const int t   = g_tbin[y];

    const float* cls = (l == 0) ? c0 : (l == 1) ? c1 : (l == 2) ? c2 : c3;
    const float* box = (l == 0) ? bx0 : (l == 1) ? bx1 : (l == 2) ? bx2 : bx3;
    const float* anc = (l == 0) ? an0 : (l == 1) ? an1 : (l == 2) ? an2 : an3;
    const int quads = c_quads[l];
    const int sh2   = c_sh2[l];
    const int HW2   = 1 << sh2;

    const float* seg  = cls + (size_t)b * ((size_t)quads << 2);
    const float* boxb = box + ((size_t)b * 36 << sh2);

    const int base = xb * QPB;
    float4 v[4];
    bool ok[4];
    #pragma unroll
    for (int k = 0; k < 4; k++) {
        int q = base + k * 256 + tid;
        ok[k] = (q < quads);
        if (ok[k]) v[k] = *(const float4*)(seg + ((size_t)q << 2));
    }
    #pragma unroll
    for (int k = 0; k < 4; k++) {
        if (!ok[k]) continue;
        const int q = base + k * 256 + tid;
        const float* pv = (const float*)&v[k];
        #pragma unroll
        for (int i = 0; i < 4; i++) {
            float lgt = pv[i];
            if (lgt > 0.0f && logit_bin(lgt) >= t) {
                // exact reference mask
                float sc = __fdiv_rn(1.0f, __fadd_rn(1.0f, expf(-lgt)));
                int n   = (q << 2) + i;
                int a   = n >> sh2;
                int pix = n & (HW2 - 1);
                const float* bp = boxb + (((size_t)a * 4) << sh2) + pix;
                float d0 = __ldg(bp);
                float d1 = __ldg(bp + HW2);
                float d2 = __ldg(bp + 2 * HW2);
                float d3 = __ldg(bp + 3 * HW2);
                float4 A = *(const float4*)(anc + ((size_t)n << 2));
                float x1, y1c, x2, y2; bool valid;
                decode_box(A, d0, d1, d2, d3, x1, y1c, x2, y2, valid);
                if (valid && sc > 0.5f) {
                    int pos = atomicAdd(&g_cnt[y * 32], 1);
                    if (pos < CAP) {
                        g_keys[(size_t)y * CAP + pos] =
                            ((unsigned long long)__float_as_uint(sc) << 32) |
                            (unsigned long long)(~(unsigned int)n);
                    }
                }
            }
        }
    }
}

// ---------------------------------------------------------------------------
// Pass 3: register bitonic sort + decode + on-demand-row greedy NMS.
// One block (1024 threads) per (b,level).
// ---------------------------------------------------------------------------
__global__ __launch_bounds__(1024) void nms_kernel(
    const float* __restrict__ bx0, const float* __restrict__ bx1,
    const float* __restrict__ bx2, const float* __restrict__ bx3,
    const float* __restrict__ an0, const float* __restrict__ an1,
    const float* __restrict__ an2, const float* __restrict__ an3,
    float* __restrict__ out, int out_size)
{
    __shared__ unsigned long long sbuf[CAP];
    __shared__ float sx1[KPRE], sy1[KPRE], sx2[KPRE], sy2[KPRE], ssc[KPRE], sar[KPRE];
    __shared__ unsigned long long rm[5];       // running suppression mask
    __shared__ int keptIdx[KOUT];
    __shared__ int s_next, s_kc;

    const int bl  = blockIdx.x;
    const int b   = bl >> 2;
    const int lvl = bl & 3;
    const int tid = threadIdx.x;

    const int M = min(g_cnt[bl * 32], CAP);
    unsigned long long v = (tid < M) ? g_keys[(size_t)bl * CAP + tid] : 0ULL;

    // ---- bitonic sort, descending; key[tid] lives in register v ----
    #pragma unroll
    for (int k = 2; k <= CAP; k <<= 1) {
        for (int j = k >> 1; j >= 32; j >>= 1) {
            sbuf[tid] = v;
            __syncthreads();
            unsigned long long u = sbuf[tid ^ j];
            bool lower   = (tid & j) == 0;
            bool blockUp = (tid & k) == 0;
            bool wantMax = (lower == blockUp);
            v = ((v > u) == wantMax) ? v : u;
            __syncthreads();
        }
        int jmax = (k >> 1) < 16 ? (k >> 1) : 16;
        for (int j = jmax; j >= 1; j >>= 1) {
            unsigned long long u = __shfl_xor_sync(0xFFFFFFFFu, v, j);
            bool lower   = (tid & j) == 0;
            bool blockUp = (tid & k) == 0;
            bool wantMax = (lower == blockUp);
            v = ((v > u) == wantMax) ? v : u;
        }
    }

    const int K = min(M, KPRE);
    const float* BX = (lvl == 0) ? bx0 : (lvl == 1) ? bx1 : (lvl == 2) ? bx2 : bx3;
    const float* AN = (lvl == 0) ? an0 : (lvl == 1) ? an1 : (lvl == 2) ? an2 : an3;
    const int sh2   = c_sh2[lvl];
    const int HW2   = 1 << sh2;

    // ---- decode top-K: thread tid owns sorted element tid ----
    if (tid < K) {
        unsigned int n = ~((unsigned int)v);
        float sc = __uint_as_float((unsigned int)(v >> 32));
        int a   = (int)(n >> sh2);
        int pix = (int)(n & (HW2 - 1));
        const float* bp = BX + (((size_t)b * 36 + (size_t)a * 4) << sh2) + pix;
        float d0 = __ldg(bp);
        float d1 = __ldg(bp + HW2);
        float d2 = __ldg(bp + 2 * HW2);
        float d3 = __ldg(bp + 3 * HW2);
        float4 A = *(const float4*)(AN + ((size_t)n << 2));
        float x1, y1, x2, y2; bool valid;
        decode_box(A, d0, d1, d2, d3, x1, y1, x2, y2, valid);
        sx1[tid] = x1; sy1[tid] = y1; sx2[tid] = x2; sy2[tid] = y2; ssc[tid] = sc;
        sar[tid] = __fmul_rn(__fsub_rn(x2, x1), __fsub_rn(y2, y1));
    }
    if (tid < 5) rm[tid] = 0ULL;
    if (tid == 0) { s_next = 0; s_kc = 0; }

    // ---- greedy walk with on-demand suppression rows ----
    for (;;) {
        __syncthreads();
        const int i  = s_next;
        const int kc = s_kc;
        if (i >= K || kc >= KOUT) break;

        bool supb = false;
        if (tid > i && tid < K) {
            float xx1 = fmaxf(sx1[i], sx1[tid]);
            float yy1 = fmaxf(sy1[i], sy1[tid]);
            float xx2 = fminf(sx2[i], sx2[tid]);
            float yy2 = fminf(sy2[i], sy2[tid]);
            float iw = fmaxf(__fsub_rn(xx2, xx1), 0.0f);
            float ih = fmaxf(__fsub_rn(yy2, yy1), 0.0f);
            float inter = __fmul_rn(iw, ih);
            float den = __fadd_rn(__fsub_rn(__fadd_rn(sar[i], sar[tid]), inter), 1e-9f);
            supb = (__fdiv_rn(inter, den) > 0.3f);
        }
        unsigned int bal = __ballot_sync(0xFFFFFFFFu, supb);
        if ((tid & 31) == 0 && bal) {
            unsigned long long w64 = (unsigned long long)bal << (tid & 32);
            atomicOr(&rm[tid >> 6], w64);
        }
        if (tid == 0) keptIdx[kc] = i;
        __syncthreads();
        if (tid == 0) {
            s_kc = kc + 1;
            int j = i + 1;
            while (j < K && ((rm[j >> 6] >> (j & 63)) & 1ULL)) j++;
            s_next = j;
        }
    }
    const int keptCnt = s_kc;

    if (tid < KOUT) {
        float o0 = 0.f, o1 = 0.f, o2 = 0.f, o3 = 0.f, o4 = 0.f, vv = 0.f;
        if (tid < keptCnt) {
            int i = keptIdx[tid];
            o0 = sx1[i]; o1 = sy1[i]; o2 = sx2[i]; o3 = sy2[i]; o4 = ssc[i];
            vv = 1.0f;
        }
        size_t row = (size_t)b * 40 + lvl * 10 + tid;
        out[row * 5 + 0] = o0;
        out[row * 5 + 1] = o1;
        out[row * 5 + 2] = o2;
        out[row * 5 + 3] = o3;
        out[row * 5 + 4] = o4;
        if (out_size >= BATCH * 40 * 5 + BATCH * 40)
            out[(size_t)BATCH * 40 * 5 + row] = vv;   // valid mask as float
    }
}

// ---------------------------------------------------------------------------
extern "C" void kernel_launch(void* const* d_in, const int* in_sizes, int n_in,
                              void* d_out, int out_size)
{
    const float *cls[4], *box[4], *anc[4];
    bool interleaved = (n_in >= 2) && (in_sizes[1] == 4 * in_sizes[0]);
    for (int l = 0; l < 4; l++) {
        if (interleaved) {
            cls[l] = (const float*)d_in[3 * l + 0];
            box[l] = (const float*)d_in[3 * l + 1];
            anc[l] = (const float*)d_in[3 * l + 2];
        } else {
            cls[l] = (const float*)d_in[l];
            box[l] = (const float*)d_in[4 + l];
            anc[l] = (const float*)d_in[8 + l];
        }
    }

    score_kernel<<<NBLK, 256>>>(cls[0], cls[1], cls[2], cls[3]);
    compact_kernel<<<NBLK, 256>>>(cls[0], cls[1], cls[2], cls[3],
                                  box[0], box[1], box[2], box[3],
                                  anc[0], anc[1], anc[2], anc[3]);
    nms_kernel<<<64, 1024>>>(box[0], box[1], box[2], box[3],
                             anc[0], anc[1], anc[2], anc[3],
                             (float*)d_out, out_size);
}